// round 2
// baseline (speedup 1.0000x reference)
#include <cuda_runtime.h>
#include <math.h>

#define NB     2048      // batch
#define NDIM   512       // dim
#define NTOK   64        // 8*8 tokens
#define NCODE  1024      // embed table rows
#define NA     16384     // codebook size

// ---------------- scratch (device globals: no allocation allowed) ----------
__device__ float g_h [NB * 1024];   // [B, 2*dim] concat pooled embeddings
__device__ float g_h2[NB * NDIM];   // after GEMM1+GELU
__device__ float g_e [NB * NDIM];   // after GEMM2
__device__ float g_cnorm[NA];       // ||codebook_row||^2
__device__ unsigned long long g_minkey[NB];

// ---------------- helpers --------------------------------------------------
__device__ __forceinline__ unsigned int fkey(float f) {
    unsigned int u = __float_as_uint(f);
    return (u & 0x80000000u) ? ~u : (u | 0x80000000u);   // monotone float->uint
}

// ---------------- init: reset per-row argmin keys ---------------------------
__global__ void k_init() {
    int i = blockIdx.x * blockDim.x + threadIdx.x;
    if (i < NB) g_minkey[i] = 0xFFFFFFFFFFFFFFFFull;
}

// ---------------- codebook row norms: 8 rows per block (1 warp/row) --------
__global__ void k_cnorm(const float* __restrict__ cb) {
    int row  = blockIdx.x * 8 + (threadIdx.x >> 5);
    int lane = threadIdx.x & 31;
    const float* r = cb + (size_t)row * NDIM;
    float s = 0.f;
    #pragma unroll
    for (int j = lane; j < NDIM; j += 32) { float v = r[j]; s += v * v; }
    #pragma unroll
    for (int o = 16; o; o >>= 1) s += __shfl_down_sync(0xFFFFFFFFu, s, o);
    if (lane == 0) g_cnorm[row] = s;
}

// ---------------- embedding gather + mean pool ------------------------------
// grid = NB blocks, 512 threads. thread t owns dim t.
// NOTE: code grids are int32 (jax default x64-disabled downcasts int64->int32).
__global__ void k_embed(const int* __restrict__ zt,
                        const int* __restrict__ zp,
                        const float* __restrict__ ew) {
    __shared__ int codes[2 * NTOK];
    int b = blockIdx.x;
    int t = threadIdx.x;
    if (t < NTOK) {
        int c = zt[(size_t)b * NTOK + t];
        codes[t] = (c < 0) ? 0 : ((c >= NCODE) ? NCODE - 1 : c);   // safety clamp
    } else if (t < 2 * NTOK) {
        int c = zp[(size_t)b * NTOK + (t - NTOK)];
        codes[t] = (c < 0) ? 0 : ((c >= NCODE) ? NCODE - 1 : c);
    }
    __syncthreads();

    float st = 0.f, sp = 0.f;
    #pragma unroll 8
    for (int i = 0; i < NTOK; i++) {
        st += ew[(size_t)codes[i]        * NDIM + t];
        sp += ew[(size_t)codes[NTOK + i] * NDIM + t];
    }
    g_h[(size_t)b * 1024 + t]       = st * (1.f / 64.f);
    g_h[(size_t)b * 1024 + 512 + t] = sp * (1.f / 64.f);
}

// ---------------- generic fp32 GEMM: C = act(A[MxK] @ B[KxN] + bias) -------
// TM=128, TN=64, KC=16, 256 threads, 8x4 microtile.
template <bool GELU>
__global__ __launch_bounds__(256, 2)
void k_gemm(const float* __restrict__ A, const float* __restrict__ Bw,
            const float* __restrict__ bias, float* __restrict__ C,
            int N, int K) {
    __shared__ float As[16][132];
    __shared__ float Bs[16][64];
    int tid = threadIdx.x;
    int tx = tid & 15, ty = tid >> 4;          // tx: 16 col groups, ty: 16 row groups
    int m0 = blockIdx.y * 128, n0 = blockIdx.x * 64;

    float acc[8][4];
    #pragma unroll
    for (int i = 0; i < 8; i++)
        #pragma unroll
        for (int j = 0; j < 4; j++) acc[i][j] = 0.f;

    for (int k0 = 0; k0 < K; k0 += 16) {
        #pragma unroll
        for (int i = 0; i < 8; i++) {          // A tile: 128x16, transposed store
            int u = tid + i * 256;
            int c = u & 15, r = u >> 4;
            As[c][r] = A[(size_t)(m0 + r) * K + k0 + c];
        }
        #pragma unroll
        for (int i = 0; i < 4; i++) {          // B tile: 16x64, direct store
            int u = tid + i * 256;
            int kk = u >> 6, c = u & 63;
            Bs[kk][c] = Bw[(size_t)(k0 + kk) * N + n0 + c];
        }
        __syncthreads();
        #pragma unroll
        for (int kk = 0; kk < 16; kk++) {
            float4 a0 = *(const float4*)&As[kk][ty * 8];
            float4 a1 = *(const float4*)&As[kk][ty * 8 + 4];
            float4 b0 = *(const float4*)&Bs[kk][tx * 4];
            float a[8] = {a0.x, a0.y, a0.z, a0.w, a1.x, a1.y, a1.z, a1.w};
            float bv[4] = {b0.x, b0.y, b0.z, b0.w};
            #pragma unroll
            for (int i = 0; i < 8; i++)
                #pragma unroll
                for (int j = 0; j < 4; j++) acc[i][j] += a[i] * bv[j];
        }
        __syncthreads();
    }

    #pragma unroll
    for (int j = 0; j < 4; j++) {
        float bb = bias[n0 + tx * 4 + j];
        #pragma unroll
        for (int i = 0; i < 8; i++) {
            float v = acc[i][j] + bb;
            if (GELU) v = v * normcdff(v);     // exact gelu: x * Phi(x)
            C[(size_t)(m0 + ty * 8 + i) * N + n0 + tx * 4 + j] = v;
        }
    }
}

// ---------------- VQ: scores = ||c||^2 - 2 e.c, fused per-row argmin -------
// TM=128 rows, TN=128 codes, KC=16, 256 threads, 8x8 microtile.
__global__ __launch_bounds__(256, 2)
void k_vq(const float* __restrict__ E, const float* __restrict__ CB) {
    __shared__ float As[16][132];
    __shared__ float Bs[16][132];
    __shared__ unsigned long long red[128][16];
    int tid = threadIdx.x;
    int tx = tid & 15, ty = tid >> 4;
    int m0 = blockIdx.y * 128, n0 = blockIdx.x * 128;

    float acc[8][8];
    #pragma unroll
    for (int i = 0; i < 8; i++)
        #pragma unroll
        for (int j = 0; j < 8; j++) acc[i][j] = 0.f;

    for (int k0 = 0; k0 < NDIM; k0 += 16) {
        #pragma unroll
        for (int i = 0; i < 8; i++) {
            int u = tid + i * 256;
            int c = u & 15, r = u >> 4;
            As[c][r] = E [(size_t)(m0 + r) * NDIM + k0 + c];
            Bs[c][r] = CB[(size_t)(n0 + r) * NDIM + k0 + c];
        }
        __syncthreads();
        #pragma unroll
        for (int kk = 0; kk < 16; kk++) {
            float4 a0 = *(const float4*)&As[kk][ty * 8];
            float4 a1 = *(const float4*)&As[kk][ty * 8 + 4];
            float4 b0 = *(const float4*)&Bs[kk][tx * 8];
            float4 b1 = *(const float4*)&Bs[kk][tx * 8 + 4];
            float a[8] = {a0.x, a0.y, a0.z, a0.w, a1.x, a1.y, a1.z, a1.w};
            float b[8] = {b0.x, b0.y, b0.z, b0.w, b1.x, b1.y, b1.z, b1.w};
            #pragma unroll
            for (int i = 0; i < 8; i++)
                #pragma unroll
                for (int j = 0; j < 8; j++) acc[i][j] += a[i] * b[j];
        }
        __syncthreads();
    }

    // local argmin over this thread's 8 cols, per row
    #pragma unroll
    for (int i = 0; i < 8; i++) {
        float best = __int_as_float(0x7F800000);  // +inf
        int bc = 0;
        #pragma unroll
        for (int j = 0; j < 8; j++) {
            float s = g_cnorm[n0 + tx * 8 + j] - 2.0f * acc[i][j];
            if (s < best) { best = s; bc = tx * 8 + j; }
        }
        red[ty * 8 + i][tx] =
            ((unsigned long long)fkey(best) << 32) | (unsigned int)(n0 + bc);
    }
    __syncthreads();
    if (tid < 128) {
        unsigned long long k = red[tid][0];
        #pragma unroll
        for (int j = 1; j < 16; j++) {
            unsigned long long v = red[tid][j];
            k = (v < k) ? v : k;
        }
        atomicMin(&g_minkey[m0 + tid], k);
    }
}

// ---------------- output: ids (as float) then q = codebook[ids] ------------
__global__ void k_out(const float* __restrict__ cb, float* __restrict__ out) {
    int b = blockIdx.x, t = threadIdx.x;
    unsigned int id = (unsigned int)(g_minkey[b] & 0xFFFFFFFFull);
    if (id >= NA) id = 0;                       // safety clamp (never taken if VQ ran)
    if (t == 0) out[b] = (float)id;
    out[NB + (size_t)b * NDIM + t] = cb[(size_t)id * NDIM + t];
}

// ---------------------------------------------------------------------------
extern "C" void kernel_launch(void* const* d_in, const int* in_sizes, int n_in,
                              void* d_out, int out_size) {
    const int*   zt = (const int*)d_in[0];
    const int*   zp = (const int*)d_in[1];
    const float* ew = (const float*)d_in[2];
    const float* w1 = (const float*)d_in[3];
    const float* b1 = (const float*)d_in[4];
    const float* w2 = (const float*)d_in[5];
    const float* b2 = (const float*)d_in[6];
    const float* cb = (const float*)d_in[7];
    float* out = (float*)d_out;

    float *ph, *ph2, *pe;
    cudaGetSymbolAddress((void**)&ph,  g_h);
    cudaGetSymbolAddress((void**)&ph2, g_h2);
    cudaGetSymbolAddress((void**)&pe,  g_e);

    k_init <<<(NB + 255) / 256, 256>>>();
    k_cnorm<<<NA / 8, 256>>>(cb);
    k_embed<<<NB, 512>>>(zt, zp, ew);
    // GEMM1: [2048,1024] @ [1024,512] + b1, gelu
    k_gemm<true ><<<dim3(512 / 64, NB / 128), 256>>>(ph,  w1, b1, ph2, 512, 1024);
    // GEMM2: [2048,512] @ [512,512] + b2
    k_gemm<false><<<dim3(512 / 64, NB / 128), 256>>>(ph2, w2, b2, pe,  512, 512);
    // VQ: fused distance + argmin
    k_vq<<<dim3(NA / 128, NB / 128), 256>>>(pe, cb);
    k_out<<<NB, 512>>>(cb, out);
}

// round 4
// speedup vs baseline: 2.1542x; 2.1542x over previous
#include <cuda_runtime.h>
#include <cuda_bf16.h>
#include <math.h>
#include <stdint.h>

#define NB     2048
#define NDIM   512
#define NTOK   64
#define NCODE  1024
#define NA     16384
#define KSPLIT 1536            // 3 * NDIM: [eh|el|eh] . [ch|ch|cl]

// ---------------- scratch (device globals) ----------------------------------
__device__ float g_h [NB * 1024];
__device__ float g_h2[NB * NDIM];
__device__ float g_e [NB * NDIM];
__device__ float g_cnorm[NA];
__device__ unsigned long long g_minkey[NB];
__device__ __nv_bfloat16 g_A[(size_t)NB * KSPLIT];   // 6 MB
__device__ __nv_bfloat16 g_B[(size_t)NA * KSPLIT];   // 48 MB

// ---------------- helpers ----------------------------------------------------
__device__ __forceinline__ uint32_t smem_u32(const void* p) {
    uint32_t a;
    asm("{ .reg .u64 t; cvta.to.shared.u64 t, %1; cvt.u32.u64 %0, t; }" : "=r"(a) : "l"(p));
    return a;
}
__device__ __forceinline__ unsigned int fkey(float f) {
    unsigned int u = __float_as_uint(f);
    return (u & 0x80000000u) ? ~u : (u | 0x80000000u);
}
#define SW128(x) ((x) ^ (((x) >> 3) & 0x70))

#define LDSM_X4(r0, r1, r2, r3, a)                                              \
    asm volatile("ldmatrix.sync.aligned.m8n8.x4.shared.b16 {%0,%1,%2,%3}, [%4];" \
                 : "=r"(r0), "=r"(r1), "=r"(r2), "=r"(r3) : "r"(a) : "memory")

#define MMA16816(d, a, b)                                                       \
    asm volatile("mma.sync.aligned.m16n8k16.row.col.f32.bf16.bf16.f32 "         \
                 "{%0,%1,%2,%3},{%4,%5,%6,%7},{%8,%9},{%0,%1,%2,%3};"           \
                 : "+f"((d)[0]), "+f"((d)[1]), "+f"((d)[2]), "+f"((d)[3])       \
                 : "r"((a)[0]), "r"((a)[1]), "r"((a)[2]), "r"((a)[3]),          \
                   "r"((b)[0]), "r"((b)[1]))

#define CP16(dst, src) asm volatile("cp.async.cg.shared.global [%0], [%1], 16;" \
                                    :: "r"(dst), "l"(src) : "memory")
#define CPCOMMIT()     asm volatile("cp.async.commit_group;" ::: "memory")
#define CPWAIT(n)      asm volatile("cp.async.wait_group %0;" :: "n"(n) : "memory")

// ---------------- small kernels ----------------------------------------------
__global__ void k_init() {
    int i = blockIdx.x * blockDim.x + threadIdx.x;
    if (i < NB) g_minkey[i] = 0xFFFFFFFFFFFFFFFFull;
}

// codebook: norms + bf16 split  B = [ch|ch|cl]
__global__ void k_prep_cb(const float* __restrict__ cb) {
    __shared__ float red[16];
    int row = blockIdx.x, t = threadIdx.x;
    float v = cb[(size_t)row * NDIM + t];
    __nv_bfloat16 ch = __float2bfloat16(v);
    __nv_bfloat16 cl = __float2bfloat16(v - __bfloat162float(ch));
    size_t base = (size_t)row * KSPLIT;
    g_B[base + t]        = ch;
    g_B[base + 512 + t]  = ch;
    g_B[base + 1024 + t] = cl;
    float s = v * v;
    #pragma unroll
    for (int o = 16; o; o >>= 1) s += __shfl_down_sync(0xFFFFFFFFu, s, o);
    if ((t & 31) == 0) red[t >> 5] = s;
    __syncthreads();
    if (t < 16) {
        s = red[t];
        #pragma unroll
        for (int o = 8; o; o >>= 1) s += __shfl_down_sync(0xFFFFu, s, o);
        if (t == 0) g_cnorm[row] = s;
    }
}

// e split: A = [eh|el|eh]
__global__ void k_split_e() {
    int b = blockIdx.x, t = threadIdx.x;
    float v = g_e[(size_t)b * NDIM + t];
    __nv_bfloat16 eh = __float2bfloat16(v);
    __nv_bfloat16 el = __float2bfloat16(v - __bfloat162float(eh));
    size_t base = (size_t)b * KSPLIT;
    g_A[base + t]        = eh;
    g_A[base + 512 + t]  = el;
    g_A[base + 1024 + t] = eh;
}

// embedding gather + mean pool (int32 code grids)
__global__ void k_embed(const int* __restrict__ zt, const int* __restrict__ zp,
                        const float* __restrict__ ew) {
    __shared__ int codes[2 * NTOK];
    int b = blockIdx.x, t = threadIdx.x;
    if (t < NTOK) {
        int c = zt[(size_t)b * NTOK + t];
        codes[t] = (c < 0) ? 0 : ((c >= NCODE) ? NCODE - 1 : c);
    } else if (t < 2 * NTOK) {
        int c = zp[(size_t)b * NTOK + (t - NTOK)];
        codes[t] = (c < 0) ? 0 : ((c >= NCODE) ? NCODE - 1 : c);
    }
    __syncthreads();
    float st = 0.f, sp = 0.f;
    #pragma unroll 8
    for (int i = 0; i < NTOK; i++) {
        st += ew[(size_t)codes[i]        * NDIM + t];
        sp += ew[(size_t)codes[NTOK + i] * NDIM + t];
    }
    g_h[(size_t)b * 1024 + t]       = st * (1.f / 64.f);
    g_h[(size_t)b * 1024 + 512 + t] = sp * (1.f / 64.f);
}

// ---------------- fp32 MLP GEMM: 64x64 tile, 256 thr, 4x4 micro --------------
template <bool GELU>
__global__ __launch_bounds__(256)
void k_gemm(const float* __restrict__ A, const float* __restrict__ Bw,
            const float* __restrict__ bias, float* __restrict__ C,
            int N, int K) {
    __shared__ float As[16][68];
    __shared__ float Bs[16][64];
    int tid = threadIdx.x;
    int tx = tid & 15, ty = tid >> 4;
    int m0 = blockIdx.y * 64, n0 = blockIdx.x * 64;

    float acc[4][4];
    #pragma unroll
    for (int i = 0; i < 4; i++)
        #pragma unroll
        for (int j = 0; j < 4; j++) acc[i][j] = 0.f;

    for (int k0 = 0; k0 < K; k0 += 16) {
        #pragma unroll
        for (int i = 0; i < 4; i++) {
            int u = tid + i * 256;
            int c = u & 15, r = u >> 4;
            As[c][r] = A[(size_t)(m0 + r) * K + k0 + c];
        }
        #pragma unroll
        for (int i = 0; i < 4; i++) {
            int u = tid + i * 256;
            int kk = u >> 6, cc = u & 63;
            Bs[kk][cc] = Bw[(size_t)(k0 + kk) * N + n0 + cc];
        }
        __syncthreads();
        #pragma unroll
        for (int kk = 0; kk < 16; kk++) {
            float4 a4 = *(const float4*)&As[kk][ty * 4];
            float4 b4 = *(const float4*)&Bs[kk][tx * 4];
            float a[4] = {a4.x, a4.y, a4.z, a4.w};
            float b[4] = {b4.x, b4.y, b4.z, b4.w};
            #pragma unroll
            for (int i = 0; i < 4; i++)
                #pragma unroll
                for (int j = 0; j < 4; j++) acc[i][j] += a[i] * b[j];
        }
        __syncthreads();
    }
    #pragma unroll
    for (int j = 0; j < 4; j++) {
        float bb = bias[n0 + tx * 4 + j];
        #pragma unroll
        for (int i = 0; i < 4; i++) {
            float v = acc[i][j] + bb;
            if (GELU) v = v * normcdff(v);
            C[(size_t)(m0 + ty * 4 + i) * N + n0 + tx * 4 + j] = v;
        }
    }
}

// ---------------- VQ on mma.sync bf16: D = A[128,1536] @ B[128,1536]^T -------
// dyn smem: A0@0 B0@16384 A1@32768 B1@49152 | red(ull[128])@65536 | cns@66560
#define VQ_SMEM 67072
#define VQ_NCH  (KSPLIT / 64)   // 24 chunks of K=64

__device__ __forceinline__ void vq_load_chunk(uint32_t sb, int buf,
                                              int m0, int n0, int c, int tid) {
    const __nv_bfloat16* Ag = g_A;
    const __nv_bfloat16* Bg = g_B;
    uint32_t ab = sb + buf * 32768u;
    uint32_t bb = ab + 16384u;
    #pragma unroll
    for (int i = 0; i < 4; i++) {
        int u = tid + i * 256;
        int r = u >> 3, g = u & 7;
        uint32_t off = SW128((uint32_t)(r * 128 + g * 16));
        CP16(ab + off, Ag + (size_t)(m0 + r) * KSPLIT + c * 64 + g * 8);
        CP16(bb + off, Bg + (size_t)(n0 + r) * KSPLIT + c * 64 + g * 8);
    }
}

__global__ __launch_bounds__(256, 2) void k_vq_mma() {
    extern __shared__ char smem[];
    uint32_t sb = smem_u32(smem);
    unsigned long long* red = (unsigned long long*)(smem + 65536);
    float* cns = (float*)(smem + 66560);

    int tid = threadIdx.x;
    int lane = tid & 31, wid = tid >> 5;
    int warp_m = wid & 3, warp_n = wid >> 2;          // 4 (m) x 2 (n)
    int m0 = blockIdx.y * 128, n0 = blockIdx.x * 128;

    if (tid < 128) {
        red[tid] = 0xFFFFFFFFFFFFFFFFull;
        cns[tid] = g_cnorm[n0 + tid];
    }

    // per-lane ldmatrix row bases
    int j = lane >> 3, lr = lane & 7;
    int arow = warp_m * 32 + ((j & 1) << 3) + lr;     // mi=0 rows
    int ar7 = arow & 7, ajhi = j >> 1;
    int brow = warp_n * 64 + ((j >> 1) << 3) + lr;    // p=0 rows
    int br7 = brow & 7, bjlo = j & 1;

    float acc[2][8][4];
    #pragma unroll
    for (int mi = 0; mi < 2; mi++)
        #pragma unroll
        for (int nj = 0; nj < 8; nj++)
            #pragma unroll
            for (int q = 0; q < 4; q++) acc[mi][nj][q] = 0.f;

    vq_load_chunk(sb, 0, m0, n0, 0, tid);
    CPCOMMIT();

    for (int c = 0; c < VQ_NCH; c++) {
        if (c < VQ_NCH - 1) {
            vq_load_chunk(sb, (c + 1) & 1, m0, n0, c + 1, tid);
            CPCOMMIT();
            CPWAIT(1);
        } else {
            CPWAIT(0);
        }
        __syncthreads();

        uint32_t ab = sb + (uint32_t)(c & 1) * 32768u;
        uint32_t bb = ab + 16384u;
        #pragma unroll
        for (int s = 0; s < 4; s++) {
            uint32_t af[2][4];
            uint32_t aaddr = ab + (uint32_t)(arow * 128 + (((2 * s + ajhi) ^ ar7) << 4));
            LDSM_X4(af[0][0], af[0][1], af[0][2], af[0][3], aaddr);
            LDSM_X4(af[1][0], af[1][1], af[1][2], af[1][3], aaddr + 2048u);
            uint32_t bf[16];
            uint32_t baddr = bb + (uint32_t)(brow * 128 + (((2 * s + bjlo) ^ br7) << 4));
            #pragma unroll
            for (int p = 0; p < 4; p++)
                LDSM_X4(bf[4 * p], bf[4 * p + 1], bf[4 * p + 2], bf[4 * p + 3],
                        baddr + (uint32_t)(p * 2048));
            #pragma unroll
            for (int mi = 0; mi < 2; mi++)
                #pragma unroll
                for (int nj = 0; nj < 8; nj++) {
                    uint32_t b2[2] = {bf[(nj >> 1) * 4 + (nj & 1) * 2],
                                      bf[(nj >> 1) * 4 + (nj & 1) * 2 + 1]};
                    MMA16816(acc[mi][nj], af[mi], b2);
                }
        }
        __syncthreads();
    }

    // epilogue: per-row argmin of  score = ||c||^2 - 2 d
    int qr = lane >> 2, qc = lane & 3;
    #pragma unroll
    for (int mi = 0; mi < 2; mi++) {
        #pragma unroll
        for (int h = 0; h < 2; h++) {
            int rowl = warp_m * 32 + mi * 16 + h * 8 + qr;
            float best = __int_as_float(0x7F800000);
            int bi = 0;
            #pragma unroll
            for (int nj = 0; nj < 8; nj++) {
                int col = warp_n * 64 + nj * 8 + qc * 2;
                float s0 = cns[col]     - 2.0f * acc[mi][nj][h * 2 + 0];
                float s1 = cns[col + 1] - 2.0f * acc[mi][nj][h * 2 + 1];
                if (s0 < best) { best = s0; bi = col; }
                if (s1 < best) { best = s1; bi = col + 1; }
            }
            unsigned long long key =
                ((unsigned long long)fkey(best) << 32) | (unsigned int)(n0 + bi);
            #pragma unroll
            for (int off = 1; off <= 2; off <<= 1) {
                unsigned long long o = __shfl_xor_sync(0xFFFFFFFFu, key, off);
                if (o < key) key = o;
            }
            if (qc == 0) atomicMin(&red[rowl], key);
        }
    }
    __syncthreads();
    if (tid < 128) atomicMin(&g_minkey[m0 + tid], red[tid]);
}

// ---------------- output -------------------------------------------------------
__global__ void k_out(const float* __restrict__ cb, float* __restrict__ out) {
    int b = blockIdx.x, t = threadIdx.x;
    unsigned int id = (unsigned int)(g_minkey[b] & 0xFFFFFFFFull);
    if (id >= NA) id = 0;
    if (t == 0) out[b] = (float)id;
    out[NB + (size_t)b * NDIM + t] = cb[(size_t)id * NDIM + t];
}

// -------------------------------------------------------------------------------
extern "C" void kernel_launch(void* const* d_in, const int* in_sizes, int n_in,
                              void* d_out, int out_size) {
    const int*   zt = (const int*)d_in[0];
    const int*   zp = (const int*)d_in[1];
    const float* ew = (const float*)d_in[2];
    const float* w1 = (const float*)d_in[3];
    const float* b1 = (const float*)d_in[4];
    const float* w2 = (const float*)d_in[5];
    const float* b2 = (const float*)d_in[6];
    const float* cb = (const float*)d_in[7];
    float* out = (float*)d_out;

    float *ph, *ph2, *pe;
    cudaGetSymbolAddress((void**)&ph,  g_h);
    cudaGetSymbolAddress((void**)&ph2, g_h2);
    cudaGetSymbolAddress((void**)&pe,  g_e);

    cudaFuncSetAttribute(k_vq_mma, cudaFuncAttributeMaxDynamicSharedMemorySize, VQ_SMEM);

    k_init   <<<(NB + 255) / 256, 256>>>();
    k_prep_cb<<<NA, 512>>>(cb);
    k_embed  <<<NB, 512>>>(zt, zp, ew);
    k_gemm<true ><<<dim3(512 / 64, NB / 64), 256>>>(ph,  w1, b1, ph2, 512, 1024);
    k_gemm<false><<<dim3(512 / 64, NB / 64), 256>>>(ph2, w2, b2, pe,  512, 512);
    k_split_e<<<NB, 512>>>();
    k_vq_mma <<<dim3(NA / 128, NB / 128), 256, VQ_SMEM>>>();
    k_out    <<<NB, 512>>>(cb, out);
}

// round 5
// speedup vs baseline: 2.3920x; 1.1104x over previous
#include <cuda_runtime.h>
#include <cuda_bf16.h>
#include <math.h>
#include <stdint.h>

#define NB     2048
#define NDIM   512
#define NTOK   64
#define NCODE  1024
#define NA     16384
#define KSPLIT 1536            // 3 * NDIM: [eh|el|eh] . [ch|ch|cl]
#define KH1    3072            // 3 * 1024 for GEMM1

// ---------------- scratch (device globals) ----------------------------------
__device__ float g_cnorm[NA];
__device__ unsigned long long g_minkey[NB];
__device__ __nv_bfloat16 g_hA [(size_t)NB * KH1];     // 12 MB  [hh|hl|hh]
__device__ __nv_bfloat16 g_h2A[(size_t)NB * KSPLIT];  //  6 MB  [h2h|h2l|h2h]
__device__ __nv_bfloat16 g_A  [(size_t)NB * KSPLIT];  //  6 MB  [eh|el|eh]
__device__ __nv_bfloat16 g_B  [(size_t)NA * KSPLIT];  // 48 MB  [ch|ch|cl]
__device__ __nv_bfloat16 g_w1s[(size_t)512 * KH1];    //  3 MB  w1^T split
__device__ __nv_bfloat16 g_w2s[(size_t)512 * KSPLIT]; // 1.5 MB w2^T split

// ---------------- helpers ----------------------------------------------------
__device__ __forceinline__ uint32_t smem_u32(const void* p) {
    uint32_t a;
    asm("{ .reg .u64 t; cvta.to.shared.u64 t, %1; cvt.u32.u64 %0, t; }" : "=r"(a) : "l"(p));
    return a;
}
__device__ __forceinline__ unsigned int fkey(float f) {
    unsigned int u = __float_as_uint(f);
    return (u & 0x80000000u) ? ~u : (u | 0x80000000u);
}
#define SW128(x) ((x) ^ (((x) >> 3) & 0x70))

#define LDSM_X4(r0, r1, r2, r3, a)                                              \
    asm volatile("ldmatrix.sync.aligned.m8n8.x4.shared.b16 {%0,%1,%2,%3}, [%4];" \
                 : "=r"(r0), "=r"(r1), "=r"(r2), "=r"(r3) : "r"(a) : "memory")

#define MMA16816(d, a, b)                                                       \
    asm volatile("mma.sync.aligned.m16n8k16.row.col.f32.bf16.bf16.f32 "         \
                 "{%0,%1,%2,%3},{%4,%5,%6,%7},{%8,%9},{%0,%1,%2,%3};"           \
                 : "+f"((d)[0]), "+f"((d)[1]), "+f"((d)[2]), "+f"((d)[3])       \
                 : "r"((a)[0]), "r"((a)[1]), "r"((a)[2]), "r"((a)[3]),          \
                   "r"((b)[0]), "r"((b)[1]))

#define CP16(dst, src) asm volatile("cp.async.cg.shared.global [%0], [%1], 16;" \
                                    :: "r"(dst), "l"(src) : "memory")
#define CPCOMMIT()     asm volatile("cp.async.commit_group;" ::: "memory")
#define CPWAIT(n)      asm volatile("cp.async.wait_group %0;" :: "n"(n) : "memory")

// shared tile loader: A[128 rows from m0, strideA], B[128 rows from n0, strideB],
// 64-col chunk c. buf selects ping/pong (32KB apart; A at +0, B at +16KB).
__device__ __forceinline__ void load_tile_chunk(uint32_t sb, int buf,
        const __nv_bfloat16* __restrict__ Ag, const __nv_bfloat16* __restrict__ Bg,
        int strideA, int strideB, int m0, int n0, int c, int tid) {
    uint32_t ab = sb + (uint32_t)buf * 32768u;
    uint32_t bb = ab + 16384u;
    #pragma unroll
    for (int i = 0; i < 4; i++) {
        int u = tid + i * 256;
        int r = u >> 3, g = u & 7;
        uint32_t off = SW128((uint32_t)(r * 128 + g * 16));
        CP16(ab + off, Ag + (size_t)(m0 + r) * strideA + c * 64 + g * 8);
        CP16(bb + off, Bg + (size_t)(n0 + r) * strideB + c * 64 + g * 8);
    }
}

// ---------------- small kernels ----------------------------------------------
__global__ void k_init() {
    int i = blockIdx.x * blockDim.x + threadIdx.x;
    if (i < NB) g_minkey[i] = 0xFFFFFFFFFFFFFFFFull;
}

// codebook: norms + bf16 split  B = [ch|ch|cl]
__global__ void k_prep_cb(const float* __restrict__ cb) {
    __shared__ float red[16];
    int row = blockIdx.x, t = threadIdx.x;
    float v = cb[(size_t)row * NDIM + t];
    __nv_bfloat16 ch = __float2bfloat16(v);
    __nv_bfloat16 cl = __float2bfloat16(v - __bfloat162float(ch));
    size_t base = (size_t)row * KSPLIT;
    g_B[base + t]        = ch;
    g_B[base + 512 + t]  = ch;
    g_B[base + 1024 + t] = cl;
    float s = v * v;
    #pragma unroll
    for (int o = 16; o; o >>= 1) s += __shfl_down_sync(0xFFFFFFFFu, s, o);
    if ((t & 31) == 0) red[t >> 5] = s;
    __syncthreads();
    if (t < 16) {
        s = red[t];
        #pragma unroll
        for (int o = 8; o; o >>= 1) s += __shfl_down_sync(0xFFFFu, s, o);
        if (t == 0) g_cnorm[row] = s;
    }
}

// weight transpose+split: ws[n, k] over 3 segments [wh|wh|wl], K rows in w
__global__ void k_prep_w(const float* __restrict__ w, __nv_bfloat16* __restrict__ ws,
                         int K) {
    int n = blockIdx.x;                    // 512 blocks
    int kt = K * 3;
    for (int k = threadIdx.x; k < K; k += blockDim.x) {
        float v = w[(size_t)k * 512 + n];
        __nv_bfloat16 h = __float2bfloat16(v);
        __nv_bfloat16 l = __float2bfloat16(v - __bfloat162float(h));
        size_t base = (size_t)n * kt;
        ws[base + k]         = h;
        ws[base + K + k]     = h;
        ws[base + 2 * K + k] = l;
    }
}

// embedding gather + mean pool -> split h directly: hA = [hh(1024)|hl|hh]
__global__ void k_embed(const int* __restrict__ zt, const int* __restrict__ zp,
                        const float* __restrict__ ew) {
    __shared__ int codes[2 * NTOK];
    int b = blockIdx.x, t = threadIdx.x;
    if (t < NTOK) {
        int c = zt[(size_t)b * NTOK + t];
        codes[t] = (c < 0) ? 0 : ((c >= NCODE) ? NCODE - 1 : c);
    } else if (t < 2 * NTOK) {
        int c = zp[(size_t)b * NTOK + (t - NTOK)];
        codes[t] = (c < 0) ? 0 : ((c >= NCODE) ? NCODE - 1 : c);
    }
    __syncthreads();
    float st = 0.f, sp = 0.f;
    #pragma unroll 8
    for (int i = 0; i < NTOK; i++) {
        st += ew[(size_t)codes[i]        * NDIM + t];
        sp += ew[(size_t)codes[NTOK + i] * NDIM + t];
    }
    st *= (1.f / 64.f); sp *= (1.f / 64.f);
    __nv_bfloat16 sh = __float2bfloat16(st);
    __nv_bfloat16 sl = __float2bfloat16(st - __bfloat162float(sh));
    __nv_bfloat16 ph = __float2bfloat16(sp);
    __nv_bfloat16 pl = __float2bfloat16(sp - __bfloat162float(ph));
    size_t base = (size_t)b * KH1;
    g_hA[base + t]              = sh;   // seg0: cols 0..511 = e_t high
    g_hA[base + 512 + t]        = ph;   //       cols 512..1023 = e_tp1 high
    g_hA[base + 1024 + t]       = sl;   // seg1: lows
    g_hA[base + 1536 + t]       = pl;
    g_hA[base + 2048 + t]       = sh;   // seg2: highs again
    g_hA[base + 2560 + t]       = ph;
}

// ---------------- MLP GEMM on mma.sync: out = act(A @ B^T + bias), split-out --
// A [2048, K] split rows; B [512, K] split rows; out [2048, 3*(K? no: 1536)] split.
// Tile 128x128, 8 warps (4m x 2n), KC=64 double-buffered.
// dyn smem: A0@0 B0@16384 A1@32768 B1@49152 bias@65536 (128 floats)
#define MLP_SMEM 66048
template <bool GELU>
__global__ __launch_bounds__(256)
void k_mlp(const __nv_bfloat16* __restrict__ Ag, const __nv_bfloat16* __restrict__ Bg,
           const float* __restrict__ bias, __nv_bfloat16* __restrict__ outS, int K) {
    extern __shared__ char smem[];
    uint32_t sb = smem_u32(smem);
    float* bias_s = (float*)(smem + 65536);

    int tid = threadIdx.x;
    int lane = tid & 31, wid = tid >> 5;
    int warp_m = wid & 3, warp_n = wid >> 2;
    int m0 = blockIdx.y * 128, n0 = blockIdx.x * 128;
    int nch = K / 64;

    if (tid < 128) bias_s[tid] = bias[n0 + tid];

    int j = lane >> 3, lr = lane & 7;
    int arow = warp_m * 32 + ((j & 1) << 3) + lr;
    int ar7 = arow & 7, ajhi = j >> 1;
    int brow = warp_n * 64 + ((j >> 1) << 3) + lr;
    int br7 = brow & 7, bjlo = j & 1;

    float acc[2][8][4];
    #pragma unroll
    for (int mi = 0; mi < 2; mi++)
        #pragma unroll
        for (int nj = 0; nj < 8; nj++)
            #pragma unroll
            for (int q = 0; q < 4; q++) acc[mi][nj][q] = 0.f;

    load_tile_chunk(sb, 0, Ag, Bg, K, K, m0, n0, 0, tid);
    CPCOMMIT();

    for (int c = 0; c < nch; c++) {
        if (c < nch - 1) {
            load_tile_chunk(sb, (c + 1) & 1, Ag, Bg, K, K, m0, n0, c + 1, tid);
            CPCOMMIT();
            CPWAIT(1);
        } else {
            CPWAIT(0);
        }
        __syncthreads();
        uint32_t ab = sb + (uint32_t)(c & 1) * 32768u;
        uint32_t bb = ab + 16384u;
        #pragma unroll
        for (int s = 0; s < 4; s++) {
            uint32_t af[2][4];
            uint32_t aaddr = ab + (uint32_t)(arow * 128 + (((2 * s + ajhi) ^ ar7) << 4));
            LDSM_X4(af[0][0], af[0][1], af[0][2], af[0][3], aaddr);
            LDSM_X4(af[1][0], af[1][1], af[1][2], af[1][3], aaddr + 2048u);
            uint32_t bf[16];
            uint32_t baddr = bb + (uint32_t)(brow * 128 + (((2 * s + bjlo) ^ br7) << 4));
            #pragma unroll
            for (int p = 0; p < 4; p++)
                LDSM_X4(bf[4 * p], bf[4 * p + 1], bf[4 * p + 2], bf[4 * p + 3],
                        baddr + (uint32_t)(p * 2048));
            #pragma unroll
            for (int mi = 0; mi < 2; mi++)
                #pragma unroll
                for (int nj = 0; nj < 8; nj++) {
                    uint32_t b2[2] = {bf[(nj >> 1) * 4 + (nj & 1) * 2],
                                      bf[(nj >> 1) * 4 + (nj & 1) * 2 + 1]};
                    MMA16816(acc[mi][nj], af[mi], b2);
                }
        }
        __syncthreads();
    }

    // epilogue: bias (+gelu), 3-term split-store into outS rows of width 1536
    int qr = lane >> 2, qc = lane & 3;
    #pragma unroll
    for (int mi = 0; mi < 2; mi++) {
        #pragma unroll
        for (int h = 0; h < 2; h++) {
            int row = m0 + warp_m * 32 + mi * 16 + h * 8 + qr;
            #pragma unroll
            for (int nj = 0; nj < 8; nj++) {
                int lc = warp_n * 64 + nj * 8 + qc * 2;   // local col in [0,128)
                float v0 = acc[mi][nj][h * 2 + 0] + bias_s[lc];
                float v1 = acc[mi][nj][h * 2 + 1] + bias_s[lc + 1];
                if (GELU) { v0 = v0 * normcdff(v0); v1 = v1 * normcdff(v1); }
                __nv_bfloat16 h0 = __float2bfloat16(v0);
                __nv_bfloat16 h1 = __float2bfloat16(v1);
                __nv_bfloat16 l0 = __float2bfloat16(v0 - __bfloat162float(h0));
                __nv_bfloat16 l1 = __float2bfloat16(v1 - __bfloat162float(h1));
                __nv_bfloat162 ph; ph.x = h0; ph.y = h1;
                __nv_bfloat162 pl; pl.x = l0; pl.y = l1;
                int gc = n0 + lc;
                __nv_bfloat162* base = (__nv_bfloat162*)(outS + (size_t)row * KSPLIT + gc);
                base[0]          = ph;               // seg0 high
                *(__nv_bfloat162*)((__nv_bfloat16*)base + 512)  = pl;   // seg1 low
                *(__nv_bfloat162*)((__nv_bfloat16*)base + 1024) = ph;   // seg2 high
            }
        }
    }
}

// ---------------- VQ on mma.sync bf16 (unchanged from round 4) ----------------
#define VQ_SMEM 67072
#define VQ_NCH  (KSPLIT / 64)

__global__ __launch_bounds__(256, 2) void k_vq_mma() {
    extern __shared__ char smem[];
    uint32_t sb = smem_u32(smem);
    unsigned long long* red = (unsigned long long*)(smem + 65536);
    float* cns = (float*)(smem + 66560);

    int tid = threadIdx.x;
    int lane = tid & 31, wid = tid >> 5;
    int warp_m = wid & 3, warp_n = wid >> 2;
    int m0 = blockIdx.y * 128, n0 = blockIdx.x * 128;

    if (tid < 128) {
        red[tid] = 0xFFFFFFFFFFFFFFFFull;
        cns[tid] = g_cnorm[n0 + tid];
    }

    int j = lane >> 3, lr = lane & 7;
    int arow = warp_m * 32 + ((j & 1) << 3) + lr;
    int ar7 = arow & 7, ajhi = j >> 1;
    int brow = warp_n * 64 + ((j >> 1) << 3) + lr;
    int br7 = brow & 7, bjlo = j & 1;

    float acc[2][8][4];
    #pragma unroll
    for (int mi = 0; mi < 2; mi++)
        #pragma unroll
        for (int nj = 0; nj < 8; nj++)
            #pragma unroll
            for (int q = 0; q < 4; q++) acc[mi][nj][q] = 0.f;

    load_tile_chunk(sb, 0, g_A, g_B, KSPLIT, KSPLIT, m0, n0, 0, tid);
    CPCOMMIT();

    for (int c = 0; c < VQ_NCH; c++) {
        if (c < VQ_NCH - 1) {
            load_tile_chunk(sb, (c + 1) & 1, g_A, g_B, KSPLIT, KSPLIT, m0, n0, c + 1, tid);
            CPCOMMIT();
            CPWAIT(1);
        } else {
            CPWAIT(0);
        }
        __syncthreads();

        uint32_t ab = sb + (uint32_t)(c & 1) * 32768u;
        uint32_t bb = ab + 16384u;
        #pragma unroll
        for (int s = 0; s < 4; s++) {
            uint32_t af[2][4];
            uint32_t aaddr = ab + (uint32_t)(arow * 128 + (((2 * s + ajhi) ^ ar7) << 4));
            LDSM_X4(af[0][0], af[0][1], af[0][2], af[0][3], aaddr);
            LDSM_X4(af[1][0], af[1][1], af[1][2], af[1][3], aaddr + 2048u);
            uint32_t bf[16];
            uint32_t baddr = bb + (uint32_t)(brow * 128 + (((2 * s + bjlo) ^ br7) << 4));
            #pragma unroll
            for (int p = 0; p < 4; p++)
                LDSM_X4(bf[4 * p], bf[4 * p + 1], bf[4 * p + 2], bf[4 * p + 3],
                        baddr + (uint32_t)(p * 2048));
            #pragma unroll
            for (int mi = 0; mi < 2; mi++)
                #pragma unroll
                for (int nj = 0; nj < 8; nj++) {
                    uint32_t b2[2] = {bf[(nj >> 1) * 4 + (nj & 1) * 2],
                                      bf[(nj >> 1) * 4 + (nj & 1) * 2 + 1]};
                    MMA16816(acc[mi][nj], af[mi], b2);
                }
        }
        __syncthreads();
    }

    int qr = lane >> 2, qc = lane & 3;
    #pragma unroll
    for (int mi = 0; mi < 2; mi++) {
        #pragma unroll
        for (int h = 0; h < 2; h++) {
            int rowl = warp_m * 32 + mi * 16 + h * 8 + qr;
            float best = __int_as_float(0x7F800000);
            int bi = 0;
            #pragma unroll
            for (int nj = 0; nj < 8; nj++) {
                int col = warp_n * 64 + nj * 8 + qc * 2;
                float s0 = cns[col]     - 2.0f * acc[mi][nj][h * 2 + 0];
                float s1 = cns[col + 1] - 2.0f * acc[mi][nj][h * 2 + 1];
                if (s0 < best) { best = s0; bi = col; }
                if (s1 < best) { best = s1; bi = col + 1; }
            }
            unsigned long long key =
                ((unsigned long long)fkey(best) << 32) | (unsigned int)(n0 + bi);
            #pragma unroll
            for (int off = 1; off <= 2; off <<= 1) {
                unsigned long long o = __shfl_xor_sync(0xFFFFFFFFu, key, off);
                if (o < key) key = o;
            }
            if (qc == 0) atomicMin(&red[rowl], key);
        }
    }
    __syncthreads();
    if (tid < 128) atomicMin(&g_minkey[m0 + tid], red[tid]);
}

// ---------------- output -------------------------------------------------------
__global__ void k_out(const float* __restrict__ cb, float* __restrict__ out) {
    int b = blockIdx.x, t = threadIdx.x;
    unsigned int id = (unsigned int)(g_minkey[b] & 0xFFFFFFFFull);
    if (id >= NA) id = 0;
    if (t == 0) out[b] = (float)id;
    out[NB + (size_t)b * NDIM + t] = cb[(size_t)id * NDIM + t];
}

// -------------------------------------------------------------------------------
extern "C" void kernel_launch(void* const* d_in, const int* in_sizes, int n_in,
                              void* d_out, int out_size) {
    const int*   zt = (const int*)d_in[0];
    const int*   zp = (const int*)d_in[1];
    const float* ew = (const float*)d_in[2];
    const float* w1 = (const float*)d_in[3];
    const float* b1 = (const float*)d_in[4];
    const float* w2 = (const float*)d_in[5];
    const float* b2 = (const float*)d_in[6];
    const float* cb = (const float*)d_in[7];
    float* out = (float*)d_out;

    __nv_bfloat16 *phA, *ph2A, *pA, *pw1s, *pw2s;
    cudaGetSymbolAddress((void**)&phA,  g_hA);
    cudaGetSymbolAddress((void**)&ph2A, g_h2A);
    cudaGetSymbolAddress((void**)&pA,   g_A);
    cudaGetSymbolAddress((void**)&pw1s, g_w1s);
    cudaGetSymbolAddress((void**)&pw2s, g_w2s);

    cudaFuncSetAttribute(k_vq_mma, cudaFuncAttributeMaxDynamicSharedMemorySize, VQ_SMEM);
    cudaFuncSetAttribute(k_mlp<true >, cudaFuncAttributeMaxDynamicSharedMemorySize, MLP_SMEM);
    cudaFuncSetAttribute(k_mlp<false>, cudaFuncAttributeMaxDynamicSharedMemorySize, MLP_SMEM);

    k_init   <<<(NB + 255) / 256, 256>>>();
    k_prep_cb<<<NA, 512>>>(cb);
    k_prep_w <<<512, 256>>>(w1, pw1s, 1024);
    k_prep_w <<<512, 256>>>(w2, pw2s, 512);
    k_embed  <<<NB, 512>>>(zt, zp, ew);
    k_mlp<true ><<<dim3(4, NB / 128), 256, MLP_SMEM>>>(phA,  pw1s, b1, ph2A, KH1);
    k_mlp<false><<<dim3(4, NB / 128), 256, MLP_SMEM>>>(ph2A, pw2s, b2, pA,   KSPLIT);
    k_vq_mma <<<dim3(NA / 128, NB / 128), 256, VQ_SMEM>>>();
    k_out    <<<NB, 512>>>(cb, out);
}